// round 4
// baseline (speedup 1.0000x reference)
#include <cuda_runtime.h>
#include <cstdint>

#define Bb 64
#define Nn 64
#define KDIM 512
#define NOUT 480           // NT*SEM = 30*16
#define NT 30
#define ROWS 4096
#define NSPAN 2016
#define NP1 65

// Scratch — __device__ globals (no allocation allowed)
__device__ float g_h[ROWS * NOUT];            // 7.86 MB
__device__ float g_prefix[Bb * NP1 * NOUT];   // 7.99 MB

// ---------------------------------------------------------------------------
// Kernel 1: fused gather + GEMM  h = emb[x] @ w_out^T + b_out
// BM=64, BN=96, BK=16, 96 threads. Thread tile 8m(4 pairs) x 8n, FFMA2.
// 2D thread layout (ty,tx) makes smem a/b loads mostly warp-broadcast.
// ---------------------------------------------------------------------------
#define BM 64
#define BN 96
#define BK 16
#define GTH 96
#define ASTRIDE 68

__global__ __launch_bounds__(GTH) void gemm_kernel(
    const int* __restrict__ x, const float* __restrict__ emb,
    const float* __restrict__ w, const float* __restrict__ bo)
{
    __shared__ __align__(16) float As[BK][ASTRIDE];   // k-major: As[k][m]
    __shared__ __align__(16) float Ws[BK][BN];        // k-major: Ws[k][n]
    __shared__ int rowidx[BM];

    const int tid = threadIdx.x;
    const int m0 = blockIdx.x * BM;
    const int n0 = blockIdx.y * BN;

    if (tid < BM) rowidx[tid] = x[m0 + tid];
    __syncthreads();

    const int tx = tid % 12;   // n group: cols tx*8
    const int ty = tid / 12;   // m group: rows ty*8 (4 pairs)

    unsigned long long acc[4][8];
#pragma unroll
    for (int p = 0; p < 4; p++)
#pragma unroll
        for (int j = 0; j < 8; j++) acc[p][j] = 0ull;

    for (int kt = 0; kt < KDIM / BK; kt++) {
        // ---- fetch A (64 rows x 16 k) : 256 float4, idx -> m=idx>>2, kq=idx&3
        float4 av[3];
#pragma unroll
        for (int it = 0; it < 3; it++) {
            const int idx = tid + it * GTH;
            if (idx < 256) {
                const int m = idx >> 2, kq = idx & 3;
                av[it] = *(const float4*)(emb + (size_t)rowidx[m] * KDIM + kt * BK + kq * 4);
            }
        }
        // ---- fetch W: thread tid owns row n0+tid, 4 contiguous float4
        float4 wv[4];
#pragma unroll
        for (int it = 0; it < 4; it++)
            wv[it] = *(const float4*)(w + (size_t)(n0 + tid) * KDIM + kt * BK + it * 4);

        __syncthreads();   // previous compute done before smem overwrite

#pragma unroll
        for (int it = 0; it < 3; it++) {
            const int idx = tid + it * GTH;
            if (idx < 256) {
                const int m = idx >> 2, kq = idx & 3;
                As[kq * 4 + 0][m] = av[it].x;
                As[kq * 4 + 1][m] = av[it].y;
                As[kq * 4 + 2][m] = av[it].z;
                As[kq * 4 + 3][m] = av[it].w;
            }
        }
#pragma unroll
        for (int it = 0; it < 4; it++) {
            Ws[it * 4 + 0][tid] = wv[it].x;
            Ws[it * 4 + 1][tid] = wv[it].y;
            Ws[it * 4 + 2][tid] = wv[it].z;
            Ws[it * 4 + 3][tid] = wv[it].w;
        }
        __syncthreads();

#pragma unroll
        for (int k = 0; k < BK; k++) {
            // a: 4 m-pairs, naturally packed from k-major smem (16B aligned)
            const ulonglong2* ap = (const ulonglong2*)&As[k][ty * 8];
            const ulonglong2 a01 = ap[0];
            const ulonglong2 a23 = ap[1];
            unsigned long long a[4] = {a01.x, a01.y, a23.x, a23.y};
            // b: 8 scalars, duplicated into both f32x2 lanes
            const uint4 b0 = *(const uint4*)&Ws[k][tx * 8];
            const uint4 b1 = *(const uint4*)&Ws[k][tx * 8 + 4];
            unsigned long long bd[8];
            asm("mov.b64 %0, {%1, %1};" : "=l"(bd[0]) : "r"(b0.x));
            asm("mov.b64 %0, {%1, %1};" : "=l"(bd[1]) : "r"(b0.y));
            asm("mov.b64 %0, {%1, %1};" : "=l"(bd[2]) : "r"(b0.z));
            asm("mov.b64 %0, {%1, %1};" : "=l"(bd[3]) : "r"(b0.w));
            asm("mov.b64 %0, {%1, %1};" : "=l"(bd[4]) : "r"(b1.x));
            asm("mov.b64 %0, {%1, %1};" : "=l"(bd[5]) : "r"(b1.y));
            asm("mov.b64 %0, {%1, %1};" : "=l"(bd[6]) : "r"(b1.z));
            asm("mov.b64 %0, {%1, %1};" : "=l"(bd[7]) : "r"(b1.w));
#pragma unroll
            for (int p = 0; p < 4; p++)
#pragma unroll
                for (int j = 0; j < 8; j++)
                    asm("fma.rn.f32x2 %0, %1, %2, %0;"
                        : "+l"(acc[p][j]) : "l"(a[p]), "l"(bd[j]));
        }
    }

    // epilogue: unpack pairs, add bias, store
    const float4 ba = *(const float4*)(bo + n0 + tx * 8);
    const float4 bc = *(const float4*)(bo + n0 + tx * 8 + 4);
#pragma unroll
    for (int p = 0; p < 4; p++) {
        unsigned lo[8], hi[8];
#pragma unroll
        for (int j = 0; j < 8; j++)
            asm("mov.b64 {%0, %1}, %2;" : "=r"(lo[j]), "=r"(hi[j]) : "l"(acc[p][j]));
        const int row0 = m0 + ty * 8 + 2 * p;
        float* o0 = g_h + (size_t)row0 * NOUT + n0 + tx * 8;
        float* o1 = g_h + (size_t)(row0 + 1) * NOUT + n0 + tx * 8;
        float4 v;
        v.x = __uint_as_float(lo[0]) + ba.x;
        v.y = __uint_as_float(lo[1]) + ba.y;
        v.z = __uint_as_float(lo[2]) + ba.z;
        v.w = __uint_as_float(lo[3]) + ba.w;
        *(float4*)o0 = v;
        v.x = __uint_as_float(lo[4]) + bc.x;
        v.y = __uint_as_float(lo[5]) + bc.y;
        v.z = __uint_as_float(lo[6]) + bc.z;
        v.w = __uint_as_float(lo[7]) + bc.w;
        *(float4*)(o0 + 4) = v;
        v.x = __uint_as_float(hi[0]) + ba.x;
        v.y = __uint_as_float(hi[1]) + ba.y;
        v.z = __uint_as_float(hi[2]) + ba.z;
        v.w = __uint_as_float(hi[3]) + ba.w;
        *(float4*)o1 = v;
        v.x = __uint_as_float(hi[4]) + bc.x;
        v.y = __uint_as_float(hi[5]) + bc.y;
        v.z = __uint_as_float(hi[6]) + bc.z;
        v.w = __uint_as_float(hi[7]) + bc.w;
        *(float4*)(o1 + 4) = v;
    }
}

// ---------------------------------------------------------------------------
// Kernel 2: masked cumsum over sequence -> prefix [B, N+1, 480]
// Grid (4, 64): 4 channel chunks x 64 batches, 120 threads each.
// ---------------------------------------------------------------------------
__global__ __launch_bounds__(120) void prefix_kernel(const int* __restrict__ lengths)
{
    const int b = blockIdx.y;
    const int o = blockIdx.x * 120 + threadIdx.x;
    const int len = lengths[b];
    float acc = 0.0f;
    g_prefix[((size_t)b * NP1 + 0) * NOUT + o] = 0.0f;
#pragma unroll 8
    for (int n = 0; n < Nn; n++) {
        const float v = g_h[((size_t)b * Nn + n) * NOUT + o];
        if (n < len) acc += v;
        g_prefix[((size_t)b * NP1 + n + 1) * NOUT + o] = acc;
    }
}

// ---------------------------------------------------------------------------
// Kernel 3: span features + L2 norm, smem-tiled over 8x8 (l, r) tiles.
// ---------------------------------------------------------------------------
#define STH 256

__global__ __launch_bounds__(STH) void span_kernel(float* __restrict__ out)
{
    __shared__ float sL[8][NOUT];
    __shared__ float sR[8][NOUT];

    const int b = blockIdx.y;
    const int t = blockIdx.x;                 // 0..35, t = rt*(rt+1)/2 + lt
    int rt = 0;
    while ((rt + 1) * (rt + 2) / 2 <= t) rt++;
    const int lt = t - rt * (rt + 1) / 2;

    const int tid = threadIdx.x;
    const float* pb = g_prefix + (size_t)b * NP1 * NOUT;

    // load 16 rows x 480 floats = 1920 float4, fully dense
    for (int i4 = tid; i4 < 16 * (NOUT / 4); i4 += STH) {
        const int row = i4 / (NOUT / 4);
        const int pos = i4 % (NOUT / 4);
        const int grow = (row < 8) ? (lt * 8 + row) : (rt * 8 + (row - 8) + 1);
        const float4 v = *(const float4*)(pb + (size_t)grow * NOUT + pos * 4);
        if (row < 8) *(float4*)&sL[row][pos * 4] = v;
        else         *(float4*)&sR[row - 8][pos * 4] = v;
    }
    __syncthreads();

    const int slot = tid / 60;        // 0..3 active, 4 = spare (tid 240..255)
    const int lane = tid % 60;
    const int base = (slot < 4) ? slot : 0;
    const bool diag = (lt == rt);

#pragma unroll 4
    for (int i = 0; i < 16; i++) {
        const int sp = base + 4 * i;          // 0..63
        const int li = sp & 7;
        const int ri = sp >> 3;

        const float4* Rp = (const float4*)&sR[ri][0];
        const float4* Lp = (const float4*)&sL[li][0];
        const float4 ra = Rp[lane],      la = Lp[lane];
        const float4 rb = Rp[60 + lane], lb = Lp[60 + lane];

        float4 da, db;
        da.x = ra.x - la.x; da.y = ra.y - la.y; da.z = ra.z - la.z; da.w = ra.w - la.w;
        db.x = rb.x - lb.x; db.y = rb.y - lb.y; db.z = rb.z - lb.z; db.w = rb.w - lb.w;

        float sqA = da.x * da.x;
        sqA = fmaf(da.y, da.y, sqA); sqA = fmaf(da.z, da.z, sqA); sqA = fmaf(da.w, da.w, sqA);
        float sqB = db.x * db.x;
        sqB = fmaf(db.y, db.y, sqB); sqB = fmaf(db.z, db.z, sqB); sqB = fmaf(db.w, db.w, sqB);

        sqA += __shfl_xor_sync(0xffffffffu, sqA, 1);
        sqA += __shfl_xor_sync(0xffffffffu, sqA, 2);
        sqB += __shfl_xor_sync(0xffffffffu, sqB, 1);
        sqB += __shfl_xor_sync(0xffffffffu, sqB, 2);

        const float invA = rsqrtf(sqA);
        const float invB = rsqrtf(sqB);

        if (slot < 4 && (!diag || li < ri)) {
            const int l = lt * 8 + li;
            const int r = rt * 8 + ri;
            const int k = r - l;
            const int s = (((k - 1) * (128 - k)) >> 1) + l;
            float* op = out + (size_t)(b * NSPAN + s) * NOUT;
            float4 oa, ob;
            oa.x = da.x * invA; oa.y = da.y * invA; oa.z = da.z * invA; oa.w = da.w * invA;
            ob.x = db.x * invB; ob.y = db.y * invB; ob.z = db.z * invB; ob.w = db.w * invB;
            *(float4*)(op + lane * 4) = oa;
            *(float4*)(op + 240 + lane * 4) = ob;
        }
    }
}

// ---------------------------------------------------------------------------
extern "C" void kernel_launch(void* const* d_in, const int* in_sizes, int n_in,
                              void* d_out, int out_size)
{
    const int*   x       = (const int*)d_in[0];
    const int*   lengths = (const int*)d_in[1];
    const float* emb     = (const float*)d_in[2];
    const float* w_out   = (const float*)d_in[3];
    const float* b_out   = (const float*)d_in[4];
    float* out = (float*)d_out;

    gemm_kernel<<<dim3(ROWS / BM, NOUT / BN), GTH>>>(x, emb, w_out, b_out);
    prefix_kernel<<<dim3(4, Bb), 120>>>(lengths);
    span_kernel<<<dim3(36, Bb), STH>>>(out);
}

// round 5
// speedup vs baseline: 1.0988x; 1.0988x over previous
#include <cuda_runtime.h>
#include <cstdint>

#define Bb 64
#define Nn 64
#define KDIM 512
#define NOUT 480           // NT*SEM = 30*16
#define NT 30
#define ROWS 4096
#define NSPAN 2016
#define NP1 65

// Scratch — __device__ globals (no allocation allowed)
__device__ float g_h[ROWS * NOUT];            // 7.86 MB
__device__ float g_prefix[Bb * NP1 * NOUT];   // 7.99 MB

// ---------------------------------------------------------------------------
// Kernel 1: fused gather + GEMM  h = emb[x] @ w_out^T + b_out
// BM=64, BN=96, BK=16, 192 threads (6 warps). Thread tile 8m(4 pairs) x 4n,
// packed f32x2 FFMA2. 13 warps/SM average -> latency hidden, fma-pipe bound.
// ---------------------------------------------------------------------------
#define BM 64
#define BN 96
#define BK 16
#define GTH 192
#define ASTRIDE 68

__global__ __launch_bounds__(GTH) void gemm_kernel(
    const int* __restrict__ x, const float* __restrict__ emb,
    const float* __restrict__ w, const float* __restrict__ bo)
{
    __shared__ __align__(16) float As[BK][ASTRIDE];   // k-major: As[k][m]
    __shared__ __align__(16) float Ws[BK][BN];        // k-major: Ws[k][n]
    __shared__ int rowidx[BM];

    const int tid = threadIdx.x;
    const int m0 = blockIdx.x * BM;
    const int n0 = blockIdx.y * BN;

    if (tid < BM) rowidx[tid] = x[m0 + tid];
    __syncthreads();

    const int tx = tid % 24;   // n group: cols tx*4
    const int ty = tid / 24;   // m group: rows ty*8 (4 pairs), 0..7

    // W loader mapping: 2 float4 per thread: row tid%96, kq = (tid/96)*2 + it
    const int wrow = tid % 96;
    const int wk0 = (tid / 96) * 2;

    unsigned long long acc[4][4];
#pragma unroll
    for (int p = 0; p < 4; p++)
#pragma unroll
        for (int j = 0; j < 4; j++) acc[p][j] = 0ull;

    for (int kt = 0; kt < KDIM / BK; kt++) {
        // ---- fetch A (64 rows x 16 k) : 256 float4 -> m=idx>>2, kq=idx&3
        float4 av[2];
#pragma unroll
        for (int it = 0; it < 2; it++) {
            const int idx = tid + it * GTH;
            if (idx < 256) {
                const int m = idx >> 2, kq = idx & 3;
                av[it] = *(const float4*)(emb + (size_t)rowidx[m] * KDIM + kt * BK + kq * 4);
            }
        }
        // ---- fetch W: 384 float4 -> 2 per thread
        float4 wv[2];
#pragma unroll
        for (int it = 0; it < 2; it++)
            wv[it] = *(const float4*)(w + (size_t)(n0 + wrow) * KDIM + kt * BK + (wk0 + it) * 4);

        __syncthreads();   // previous compute done before smem overwrite

#pragma unroll
        for (int it = 0; it < 2; it++) {
            const int idx = tid + it * GTH;
            if (idx < 256) {
                const int m = idx >> 2, kq = idx & 3;
                As[kq * 4 + 0][m] = av[it].x;
                As[kq * 4 + 1][m] = av[it].y;
                As[kq * 4 + 2][m] = av[it].z;
                As[kq * 4 + 3][m] = av[it].w;
            }
        }
#pragma unroll
        for (int it = 0; it < 2; it++) {
            Ws[(wk0 + it) * 4 + 0][wrow] = wv[it].x;
            Ws[(wk0 + it) * 4 + 1][wrow] = wv[it].y;
            Ws[(wk0 + it) * 4 + 2][wrow] = wv[it].z;
            Ws[(wk0 + it) * 4 + 3][wrow] = wv[it].w;
        }
        __syncthreads();

#pragma unroll
        for (int k = 0; k < BK; k++) {
            // a: 4 m-pairs, naturally packed from k-major smem (16B aligned)
            const ulonglong2* ap = (const ulonglong2*)&As[k][ty * 8];
            const ulonglong2 a01 = ap[0];
            const ulonglong2 a23 = ap[1];
            unsigned long long a[4] = {a01.x, a01.y, a23.x, a23.y};
            // b: 4 scalars, duplicated into both f32x2 lanes
            const uint4 bu = *(const uint4*)&Ws[k][tx * 4];
            unsigned long long bd[4];
            asm("mov.b64 %0, {%1, %1};" : "=l"(bd[0]) : "r"(bu.x));
            asm("mov.b64 %0, {%1, %1};" : "=l"(bd[1]) : "r"(bu.y));
            asm("mov.b64 %0, {%1, %1};" : "=l"(bd[2]) : "r"(bu.z));
            asm("mov.b64 %0, {%1, %1};" : "=l"(bd[3]) : "r"(bu.w));
#pragma unroll
            for (int p = 0; p < 4; p++)
#pragma unroll
                for (int j = 0; j < 4; j++)
                    asm("fma.rn.f32x2 %0, %1, %2, %0;"
                        : "+l"(acc[p][j]) : "l"(a[p]), "l"(bd[j]));
        }
    }

    // epilogue: unpack pairs, add bias, store
    const float4 bb = *(const float4*)(bo + n0 + tx * 4);
#pragma unroll
    for (int p = 0; p < 4; p++) {
        unsigned lo[4], hi[4];
#pragma unroll
        for (int j = 0; j < 4; j++)
            asm("mov.b64 {%0, %1}, %2;" : "=r"(lo[j]), "=r"(hi[j]) : "l"(acc[p][j]));
        const int row0 = m0 + ty * 8 + 2 * p;
        float4 o0, o1;
        o0.x = __uint_as_float(lo[0]) + bb.x;
        o0.y = __uint_as_float(lo[1]) + bb.y;
        o0.z = __uint_as_float(lo[2]) + bb.z;
        o0.w = __uint_as_float(lo[3]) + bb.w;
        o1.x = __uint_as_float(hi[0]) + bb.x;
        o1.y = __uint_as_float(hi[1]) + bb.y;
        o1.z = __uint_as_float(hi[2]) + bb.z;
        o1.w = __uint_as_float(hi[3]) + bb.w;
        *(float4*)(g_h + (size_t)row0 * NOUT + n0 + tx * 4) = o0;
        *(float4*)(g_h + (size_t)(row0 + 1) * NOUT + n0 + tx * 4) = o1;
    }
}

// ---------------------------------------------------------------------------
// Kernel 2: masked cumsum over sequence -> prefix [B, N+1, 480]
// Grid (4, 64): 4 channel chunks x 64 batches, 120 threads each.
// ---------------------------------------------------------------------------
__global__ __launch_bounds__(120) void prefix_kernel(const int* __restrict__ lengths)
{
    const int b = blockIdx.y;
    const int o = blockIdx.x * 120 + threadIdx.x;
    const int len = lengths[b];
    float acc = 0.0f;
    g_prefix[((size_t)b * NP1 + 0) * NOUT + o] = 0.0f;
#pragma unroll 8
    for (int n = 0; n < Nn; n++) {
        const float v = g_h[((size_t)b * Nn + n) * NOUT + o];
        if (n < len) acc += v;
        g_prefix[((size_t)b * NP1 + n + 1) * NOUT + o] = acc;
    }
}

// ---------------------------------------------------------------------------
// Kernel 3: span features + L2 norm, smem-tiled over 8x8 (l, r) tiles.
// ---------------------------------------------------------------------------
#define STH 256

__global__ __launch_bounds__(STH) void span_kernel(float* __restrict__ out)
{
    __shared__ float sL[8][NOUT];
    __shared__ float sR[8][NOUT];

    const int b = blockIdx.y;
    const int t = blockIdx.x;                 // 0..35, t = rt*(rt+1)/2 + lt
    int rt = 0;
    while ((rt + 1) * (rt + 2) / 2 <= t) rt++;
    const int lt = t - rt * (rt + 1) / 2;

    const int tid = threadIdx.x;
    const float* pb = g_prefix + (size_t)b * NP1 * NOUT;

    for (int i4 = tid; i4 < 16 * (NOUT / 4); i4 += STH) {
        const int row = i4 / (NOUT / 4);
        const int pos = i4 % (NOUT / 4);
        const int grow = (row < 8) ? (lt * 8 + row) : (rt * 8 + (row - 8) + 1);
        const float4 v = *(const float4*)(pb + (size_t)grow * NOUT + pos * 4);
        if (row < 8) *(float4*)&sL[row][pos * 4] = v;
        else         *(float4*)&sR[row - 8][pos * 4] = v;
    }
    __syncthreads();

    const int slot = tid / 60;        // 0..3 active, 4 = spare (tid 240..255)
    const int lane = tid % 60;
    const int base = (slot < 4) ? slot : 0;
    const bool diag = (lt == rt);

#pragma unroll 4
    for (int i = 0; i < 16; i++) {
        const int sp = base + 4 * i;          // 0..63
        const int li = sp & 7;
        const int ri = sp >> 3;

        const float4* Rp = (const float4*)&sR[ri][0];
        const float4* Lp = (const float4*)&sL[li][0];
        const float4 ra = Rp[lane],      la = Lp[lane];
        const float4 rb = Rp[60 + lane], lb = Lp[60 + lane];

        float4 da, db;
        da.x = ra.x - la.x; da.y = ra.y - la.y; da.z = ra.z - la.z; da.w = ra.w - la.w;
        db.x = rb.x - lb.x; db.y = rb.y - lb.y; db.z = rb.z - lb.z; db.w = rb.w - lb.w;

        float sqA = da.x * da.x;
        sqA = fmaf(da.y, da.y, sqA); sqA = fmaf(da.z, da.z, sqA); sqA = fmaf(da.w, da.w, sqA);
        float sqB = db.x * db.x;
        sqB = fmaf(db.y, db.y, sqB); sqB = fmaf(db.z, db.z, sqB); sqB = fmaf(db.w, db.w, sqB);

        sqA += __shfl_xor_sync(0xffffffffu, sqA, 1);
        sqA += __shfl_xor_sync(0xffffffffu, sqA, 2);
        sqB += __shfl_xor_sync(0xffffffffu, sqB, 1);
        sqB += __shfl_xor_sync(0xffffffffu, sqB, 2);

        const float invA = rsqrtf(sqA);
        const float invB = rsqrtf(sqB);

        if (slot < 4 && (!diag || li < ri)) {
            const int l = lt * 8 + li;
            const int r = rt * 8 + ri;
            const int k = r - l;
            const int s = (((k - 1) * (128 - k)) >> 1) + l;
            float* op = out + (size_t)(b * NSPAN + s) * NOUT;
            float4 oa, ob;
            oa.x = da.x * invA; oa.y = da.y * invA; oa.z = da.z * invA; oa.w = da.w * invA;
            ob.x = db.x * invB; ob.y = db.y * invB; ob.z = db.z * invB; ob.w = db.w * invB;
            *(float4*)(op + lane * 4) = oa;
            *(float4*)(op + 240 + lane * 4) = ob;
        }
    }
}

// ---------------------------------------------------------------------------
extern "C" void kernel_launch(void* const* d_in, const int* in_sizes, int n_in,
                              void* d_out, int out_size)
{
    const int*   x       = (const int*)d_in[0];
    const int*   lengths = (const int*)d_in[1];
    const float* emb     = (const float*)d_in[2];
    const float* w_out   = (const float*)d_in[3];
    const float* b_out   = (const float*)d_in[4];
    float* out = (float*)d_out;

    gemm_kernel<<<dim3(ROWS / BM, NOUT / BN), GTH>>>(x, emb, w_out, b_out);
    prefix_kernel<<<dim3(4, Bb), 120>>>(lengths);
    span_kernel<<<dim3(36, Bb), STH>>>(out);
}